// round 9
// baseline (speedup 1.0000x reference)
#include <cuda_runtime.h>
#include <math.h>
#include <stdint.h>

#define BB 2
#define NN 128
#define HH 2
#define DM 512
#define DK 256
#define BHN 512
#define SCALE 0.005524271728019903f   // 1/sqrt(128*256)
#define OUT_ELEMS (BB*NN*NN*DM)        // 16777216

// Split-K partials for projA outputs
__device__ float g_qp0[BHN*DK];
__device__ float g_qp1[BHN*DK];
__device__ float g_kp0[BHN*DK];
__device__ float g_kp1[BHN*DK];
__device__ float g_vp0[BHN*DK];
__device__ float g_vp1[BHN*DK];
__device__ float g_bxp0[BB*NN*DK];
__device__ float g_bxp1[BB*NN*DK];

__device__ float g_A[BHN];
__device__ float g_Bq[BHN];
__device__ float g_Ck[BHN];
__device__ float g_Dd[BB*NN];
__device__ float g_Vw[BHN*2*DM];       // [(bh,j)][hp][o]
__device__ float g_Bw[BB*NN*2*DM];     // [(b,j)][hp][o]

__device__ __forceinline__ float to_tf32(float x) {
    float r; asm("cvt.rna.tf32.f32 %0, %1;" : "=f"(r) : "f"(x)); return r;
}
__device__ __forceinline__ void mma_tf32(float* c,
        uint32_t a0, uint32_t a1, uint32_t a2, uint32_t a3,
        uint32_t b0, uint32_t b1) {
    asm volatile("mma.sync.aligned.m16n8k8.row.col.f32.tf32.tf32.f32 "
        "{%0,%1,%2,%3},{%4,%5,%6,%7},{%8,%9},{%0,%1,%2,%3};"
        : "+f"(c[0]), "+f"(c[1]), "+f"(c[2]), "+f"(c[3])
        : "r"(a0), "r"(a1), "r"(a2), "r"(a3), "r"(b0), "r"(b1));
}
__device__ __forceinline__ uint32_t smem_u32(const void* p) {
    uint32_t a;
    asm("{ .reg .u64 t; cvta.to.shared.u64 t, %1; cvt.u32.u64 %0, t; }"
        : "=r"(a) : "l"(p));
    return a;
}

// ---------------------------------------------------------------------------
// tf32 64x64 block GEMM core. 256 threads (8 warps, 2x4), warp tile 32x16.
// SUM2: A operand = A[.] + A2[.] before tf32 conversion.
// ---------------------------------------------------------------------------
struct TCSmem {
    float sA[2][32][72];
    float sB[2][32][72];
};

template<int KC, bool SUM2>
__device__ __forceinline__ void gemm_tile_tc(const float* __restrict__ A,
        const float* __restrict__ A2, int astride,
        const float* __restrict__ W, int wcols, int row0, int col0,
        TCSmem& s, float cacc[2][2][4])
{
    const int t = threadIdx.x;
    const int lane = t & 31, warp = t >> 5;
    const int wm = (warp & 1) * 32, wn = (warp >> 1) * 16;
    const int gid = lane >> 2, tig = lane & 3;
    const int a_r = t >> 3;
    const int a_q = (t & 7) * 4;
    const int b_k = t >> 4;
    const int b_q = (t & 15) * 4;
    constexpr int NK = KC / 32;

    float4 ra[2], rb[2];
#pragma unroll
    for (int l = 0; l < 2; ++l) {
        size_t aoff = (size_t)(row0 + a_r + 32 * l) * astride + a_q;
        ra[l] = *(const float4*)&A[aoff];
        if (SUM2) {
            float4 x = *(const float4*)&A2[aoff];
            ra[l].x += x.x; ra[l].y += x.y; ra[l].z += x.z; ra[l].w += x.w;
        }
        rb[l] = *(const float4*)&W[(size_t)(b_k + 16 * l) * wcols + col0 + b_q];
    }
#pragma unroll
    for (int l = 0; l < 2; ++l) {
        int r = a_r + 32 * l;
        s.sA[0][a_q + 0][r] = to_tf32(ra[l].x);
        s.sA[0][a_q + 1][r] = to_tf32(ra[l].y);
        s.sA[0][a_q + 2][r] = to_tf32(ra[l].z);
        s.sA[0][a_q + 3][r] = to_tf32(ra[l].w);
        float4 tb;
        tb.x = to_tf32(rb[l].x); tb.y = to_tf32(rb[l].y);
        tb.z = to_tf32(rb[l].z); tb.w = to_tf32(rb[l].w);
        *(float4*)&s.sB[0][b_k + 16 * l][b_q] = tb;
    }
    __syncthreads();

#pragma unroll
    for (int kt = 0; kt < NK; ++kt) {
        const int cur = kt & 1, nxt = cur ^ 1;
        if (kt + 1 < NK) {
            int k0 = (kt + 1) * 32;
#pragma unroll
            for (int l = 0; l < 2; ++l) {
                size_t aoff = (size_t)(row0 + a_r + 32 * l) * astride + k0 + a_q;
                ra[l] = *(const float4*)&A[aoff];
                if (SUM2) {
                    float4 x = *(const float4*)&A2[aoff];
                    ra[l].x += x.x; ra[l].y += x.y; ra[l].z += x.z; ra[l].w += x.w;
                }
                rb[l] = *(const float4*)&W[(size_t)(k0 + b_k + 16 * l) * wcols + col0 + b_q];
            }
        }
#pragma unroll
        for (int kf = 0; kf < 32; kf += 8) {
            uint32_t af[2][4], bf[2][2];
#pragma unroll
            for (int mi = 0; mi < 2; ++mi) {
                int m0 = wm + mi * 16 + gid;
                af[mi][0] = __float_as_uint(s.sA[cur][kf + tig][m0]);
                af[mi][1] = __float_as_uint(s.sA[cur][kf + tig][m0 + 8]);
                af[mi][2] = __float_as_uint(s.sA[cur][kf + tig + 4][m0]);
                af[mi][3] = __float_as_uint(s.sA[cur][kf + tig + 4][m0 + 8]);
            }
#pragma unroll
            for (int ni = 0; ni < 2; ++ni) {
                int n0 = wn + ni * 8 + gid;
                bf[ni][0] = __float_as_uint(s.sB[cur][kf + tig][n0]);
                bf[ni][1] = __float_as_uint(s.sB[cur][kf + tig + 4][n0]);
            }
#pragma unroll
            for (int mi = 0; mi < 2; ++mi)
#pragma unroll
                for (int ni = 0; ni < 2; ++ni)
                    mma_tf32(cacc[mi][ni], af[mi][0], af[mi][1], af[mi][2], af[mi][3],
                             bf[ni][0], bf[ni][1]);
        }
        if (kt + 1 < NK) {
#pragma unroll
            for (int l = 0; l < 2; ++l) {
                int r = a_r + 32 * l;
                s.sA[nxt][a_q + 0][r] = to_tf32(ra[l].x);
                s.sA[nxt][a_q + 1][r] = to_tf32(ra[l].y);
                s.sA[nxt][a_q + 2][r] = to_tf32(ra[l].z);
                s.sA[nxt][a_q + 3][r] = to_tf32(ra[l].w);
                float4 tb;
                tb.x = to_tf32(rb[l].x); tb.y = to_tf32(rb[l].y);
                tb.z = to_tf32(rb[l].z); tb.w = to_tf32(rb[l].w);
                *(float4*)&s.sB[nxt][b_k + 16 * l][b_q] = tb;
            }
        }
        __syncthreads();
    }
}

// ---------------------------------------------------------------------------
// Stage A: fused q/k/v/bx projections, split-K. grid=(28,4,2), 256 threads.
// ---------------------------------------------------------------------------
__global__ __launch_bounds__(256) void projA_kernel(
    const float* __restrict__ query, const float* __restrict__ key,
    const float* __restrict__ value, const float* __restrict__ boxes,
    const float* __restrict__ Wq, const float* __restrict__ bq,
    const float* __restrict__ Wk, const float* __restrict__ bk,
    const float* __restrict__ Wv, const float* __restrict__ bv,
    const float* __restrict__ Wbox, const float* __restrict__ bbox)
{
    __shared__ TCSmem s;
    int ct = blockIdx.x;
    int which = ct >> 3;
    int col0 = (ct - which * 8) * 64;
    int row0 = blockIdx.y * 64;
    int z = blockIdx.z;

    const float* A; const float* W; const float* bias; float* out; int wcols;
    if      (which == 0) { A = query; W = Wq;   bias = bq;   out = z ? g_qp1  : g_qp0;  wcols = DM; }
    else if (which == 1) { A = key;   W = Wk;   bias = bk;   out = z ? g_kp1  : g_kp0;  wcols = DM; }
    else if (which == 2) { A = value; W = Wv;   bias = bv;   out = z ? g_vp1  : g_vp0;  wcols = DM; }
    else                 { A = boxes; W = Wbox; bias = bbox; out = z ? g_bxp1 : g_bxp0; wcols = DK; }

    float cacc[2][2][4];
#pragma unroll
    for (int mi = 0; mi < 2; ++mi)
#pragma unroll
        for (int ni = 0; ni < 2; ++ni)
#pragma unroll
            for (int r = 0; r < 4; ++r) cacc[mi][ni][r] = 0.f;

    gemm_tile_tc<256, false>(A + z * 256, nullptr, DM,
                             W + (size_t)z * 256 * wcols, wcols, row0, col0, s, cacc);

    const int lane = threadIdx.x & 31, warp = threadIdx.x >> 5;
    const int wm = (warp & 1) * 32, wn = (warp >> 1) * 16;
    const int gid = lane >> 2, tig = lane & 3;
#pragma unroll
    for (int mi = 0; mi < 2; ++mi)
#pragma unroll
        for (int rr = 0; rr < 2; ++rr) {
            int row = row0 + wm + mi * 16 + rr * 8 + gid;
            int b = row >> 7, n = row & 127;
#pragma unroll
            for (int ni = 0; ni < 2; ++ni) {
                int col = col0 + wn + ni * 8 + tig * 2;
                float2 v;
                float b0 = z ? 0.f : bias[col];
                float b1 = z ? 0.f : bias[col + 1];
                v.x = cacc[mi][ni][rr * 2 + 0] + b0;
                v.y = cacc[mi][ni][rr * 2 + 1] + b1;
                if (which < 3) {
                    int h = col >> 8, dk = col & 255;
                    *(float2*)&out[(((b * HH + h) * NN) + n) * DK + dk] = v;
                } else {
                    *(float2*)&out[row * DK + col] = v;
                }
            }
        }
}

// ---------------------------------------------------------------------------
// Fused Stage B + dots. Blocks 0..191: projB tiles. 192..255: dots.
// ---------------------------------------------------------------------------
__global__ __launch_bounds__(256) void projB_dots_kernel(const float* __restrict__ Wo)
{
    __shared__ TCSmem s;
    int p = blockIdx.x;

    if (p >= 192) {
        int w = threadIdx.x >> 5;
        int lane = threadIdx.x & 31;
        int bid = (p - 192) * 8 + w;
        int j = bid & 127;
        int bh = bid >> 7;
        int b = bh >> 1;

        const float4* q0 = (const float4*)(g_qp0 + (size_t)bid * DK);
        const float4* q1 = (const float4*)(g_qp1 + (size_t)bid * DK);
        const float4* k0 = (const float4*)(g_kp0 + (size_t)bid * DK);
        const float4* k1 = (const float4*)(g_kp1 + (size_t)bid * DK);
        const float4* x0 = (const float4*)(g_bxp0 + (size_t)(b * NN + j) * DK);
        const float4* x1 = (const float4*)(g_bxp1 + (size_t)(b * NN + j) * DK);

        float pa = 0.f, pb = 0.f, pc = 0.f, pd = 0.f;
#pragma unroll
        for (int u = 0; u < 2; ++u) {
            int d = lane + u * 32;
            float4 qa = q0[d], qb = q1[d], ka = k0[d], kb = k1[d], xa = x0[d], xb = x1[d];
            float4 qv, kv, bv;
            qv.x = qa.x + qb.x; qv.y = qa.y + qb.y; qv.z = qa.z + qb.z; qv.w = qa.w + qb.w;
            kv.x = ka.x + kb.x; kv.y = ka.y + kb.y; kv.z = ka.z + kb.z; kv.w = ka.w + kb.w;
            bv.x = xa.x + xb.x; bv.y = xa.y + xb.y; bv.z = xa.z + xb.z; bv.w = xa.w + xb.w;
            pa += qv.x*kv.x + qv.y*kv.y + qv.z*kv.z + qv.w*kv.w;
            pb += bv.x*kv.x + bv.y*kv.y + bv.z*kv.z + bv.w*kv.w;
            pc += qv.x*bv.x + qv.y*bv.y + qv.z*bv.z + qv.w*bv.w;
            pd += bv.x*bv.x + bv.y*bv.y + bv.z*bv.z + bv.w*bv.w;
        }
#pragma unroll
        for (int off = 16; off > 0; off >>= 1) {
            pa += __shfl_down_sync(0xffffffff, pa, off);
            pb += __shfl_down_sync(0xffffffff, pb, off);
            pc += __shfl_down_sync(0xffffffff, pc, off);
            pd += __shfl_down_sync(0xffffffff, pd, off);
        }
        if (lane == 0) {
            g_A[bid] = pa;
            g_Bq[bid] = pb;
            g_Ck[bid] = pc;
            if ((bh & 1) == 0) g_Dd[b * NN + j] = pd;
        }
        return;
    }

    int y = p >> 3;
    int col0 = (p & 7) * 64;
    const float *A, *A2; float* out; int row0, hp;
    if (y < 16) { A = g_vp0;  A2 = g_vp1;  out = g_Vw; hp = y >> 3; row0 = (y & 7) * 64; }
    else        { y -= 16; A = g_bxp0; A2 = g_bxp1; out = g_Bw; hp = y >> 2; row0 = (y & 3) * 64; }
    const float* W = Wo + (size_t)hp * DK * DM;

    float cacc[2][2][4];
#pragma unroll
    for (int mi = 0; mi < 2; ++mi)
#pragma unroll
        for (int ni = 0; ni < 2; ++ni)
#pragma unroll
            for (int r = 0; r < 4; ++r) cacc[mi][ni][r] = 0.f;

    gemm_tile_tc<DK, true>(A, A2, DK, W, DM, row0, col0, s, cacc);

    const int lane = threadIdx.x & 31, warp = threadIdx.x >> 5;
    const int wm = (warp & 1) * 32, wn = (warp >> 1) * 16;
    const int gid = lane >> 2, tig = lane & 3;
#pragma unroll
    for (int mi = 0; mi < 2; ++mi)
#pragma unroll
        for (int rr = 0; rr < 2; ++rr) {
            int row = row0 + wm + mi * 16 + rr * 8 + gid;
#pragma unroll
            for (int ni = 0; ni < 2; ++ni) {
                int col = col0 + wn + ni * 8 + tig * 2;
                float2 v;
                v.x = cacc[mi][ni][rr * 2 + 0];
                v.y = cacc[mi][ni][rr * 2 + 1];
                *(float2*)&out[(size_t)row * (2 * DM) + hp * DM + col] = v;
            }
        }
}

// ---------------------------------------------------------------------------
// Softmax: grid 128, 128 threads, warp per row.
// ---------------------------------------------------------------------------
__global__ __launch_bounds__(128) void softmax_kernel(float* __restrict__ attn_out)
{
    int warp = threadIdx.x >> 5, lane = threadIdx.x & 31;
    int t = threadIdx.x;
    int row_base = blockIdx.x * 4;
    int bh = row_base >> 7;
    int b = bh >> 1;

    __shared__ float sA[128], sCk[128];
    __shared__ float part[4];
    __shared__ float sS0;

    sA[t]  = g_A[bh * NN + t];
    sCk[t] = g_Ck[bh * NN + t];
    __syncthreads();
    {
        float v = sA[t];
#pragma unroll
        for (int off = 16; off > 0; off >>= 1)
            v += __shfl_down_sync(0xffffffff, v, off);
        if (lane == 0) part[warp] = v;
    }
    __syncthreads();
    if (t == 0) sS0 = part[0] + part[1] + part[2] + part[3];
    __syncthreads();
    float S0 = sS0;

    int n = (row_base & 127) + warp;
    float An = sA[n];
    float Bqn = g_Bq[bh * NN + n];
    float Ddn = g_Dd[b * NN + n];

    float sv[4], mx = -1e30f;
#pragma unroll
    for (int u = 0; u < 4; ++u) {
        int m = lane + u * 32;
        float x = (m == n) ? (S0 - An + Ddn)
                           : (S0 - An - sA[m] + Bqn + sCk[m]);
        sv[u] = x * SCALE;
        mx = fmaxf(mx, sv[u]);
    }
#pragma unroll
    for (int off = 16; off > 0; off >>= 1)
        mx = fmaxf(mx, __shfl_xor_sync(0xffffffff, mx, off));
    float e[4], tot = 0.f;
#pragma unroll
    for (int u = 0; u < 4; ++u) { e[u] = expf(sv[u] - mx); tot += e[u]; }
#pragma unroll
    for (int off = 16; off > 0; off >>= 1)
        tot += __shfl_xor_sync(0xffffffff, tot, off);
    float inv = 1.f / tot;
    size_t base = ((size_t)(bh * NN) + n) * NN;
#pragma unroll
    for (int u = 0; u < 4; ++u)
        attn_out[base + lane + u * 32] = e[u] * inv;
}

// ---------------------------------------------------------------------------
// Assembly via TMA bulk stores: compute rows into smem (double-buffered
// 4-row chunks), drain with cp.async.bulk shared->global (2KB per row).
// Block per (b, jp, iq): 1024 x 256. out[b,i,jp,:] = base + a0*d0 + a1*d1
// ---------------------------------------------------------------------------
__global__ __launch_bounds__(256) void assemble_kernel(
    const float* __restrict__ bo, const float* __restrict__ attn,
    float* __restrict__ out)
{
    int bid = blockIdx.x;          // ((b*128+jp)*4 + iq)
    int iq = bid & 3;
    int bjp = bid >> 2;
    int jp = bjp & 127, b = bjp >> 7;
    int h = jp >> 6, jj = jp & 63;
    int j0 = 2 * jj, j1 = j0 + 1;
    int bh = b * HH + h;

    int t = threadIdx.x;
    int lane = t & 31;
    int sub = t >> 7;
    int c4 = (t & 127) * 4;

    // lane l<16 holds a0 for it2=l; lanes 16+ hold a1
    int itn = lane & 15;
    int i_pre = iq * 32 + itn * 2 + sub;
    float aval = attn[((size_t)(bh * NN) + i_pre) * NN + j0 + (lane >> 4)];

    float4 v0 = *(const float4*)&g_Vw[(size_t)((bh * NN + j0) * 2 + 0) * DM + c4];
    float4 v1 = *(const float4*)&g_Vw[(size_t)((bh * NN + j1) * 2 + 1) * DM + c4];
    float4 w0 = *(const float4*)&g_Bw[(size_t)((b  * NN + j0) * 2 + 0) * DM + c4];
    float4 w1 = *(const float4*)&g_Bw[(size_t)((b  * NN + j1) * 2 + 1) * DM + c4];
    float4 bb = *(const float4*)&bo[c4];

    float4 rb, r0, r1;
    rb.x = v0.x + v1.x + bb.x; rb.y = v0.y + v1.y + bb.y;
    rb.z = v0.z + v1.z + bb.z; rb.w = v0.w + v1.w + bb.w;
    r0.x = w0.x - v0.x; r0.y = w0.y - v0.y; r0.z = w0.z - v0.z; r0.w = w0.w - v0.w;
    r1.x = w1.x - v1.x; r1.y = w1.y - v1.y; r1.z = w1.z - v1.z; r1.w = w1.w - v1.w;

    __shared__ __align__(16) float sbuf[2][4][512];   // 16KB
    uint32_t sbase = smem_u32(&sbuf[0][0][0]);

    // 8 chunks of 4 rows; chunk it covers it2 = 2it, 2it+1 (row = it2*2+sub)
#pragma unroll
    for (int it = 0; it < 8; ++it) {
        int buf = it & 1;
        if (it >= 2) {
            if (t == 0)
                asm volatile("cp.async.bulk.wait_group 1;" ::: "memory");
        }
        __syncthreads();   // buffer free for all threads

#pragma unroll
        for (int rr = 0; rr < 2; ++rr) {
            int it2 = it * 2 + rr;
            float a0 = __shfl_sync(0xffffffff, aval, it2);
            float a1 = __shfl_sync(0xffffffff, aval, it2 + 16);
            float4 r;
            r.x = rb.x + a0 * r0.x + a1 * r1.x;
            r.y = rb.y + a0 * r0.y + a1 * r1.y;
            r.z = rb.z + a0 * r0.z + a1 * r1.z;
            r.w = rb.w + a0 * r0.w + a1 * r1.w;
            *(float4*)&sbuf[buf][rr * 2 + sub][c4] = r;
        }
        __syncthreads();   // chunk complete in smem

        if (t == 0) {
            asm volatile("fence.proxy.async.shared::cta;" ::: "memory");
#pragma unroll
            for (int r = 0; r < 4; ++r) {
                int i = iq * 32 + it * 4 + r;
                uint64_t gaddr = (uint64_t)&out[(((size_t)(b * NN + i) * NN) + jp) * DM];
                uint32_t saddr = sbase + (uint32_t)(buf * 4 + r) * 2048u;
                asm volatile(
                    "cp.async.bulk.global.shared::cta.bulk_group [%0], [%1], %2;"
                    :: "l"(gaddr), "r"(saddr), "r"(2048u) : "memory");
            }
            asm volatile("cp.async.bulk.commit_group;" ::: "memory");
        }
    }
    if (t == 0)
        asm volatile("cp.async.bulk.wait_group 0;" ::: "memory");
}

// ---------------------------------------------------------------------------
extern "C" void kernel_launch(void* const* d_in, const int* in_sizes, int n_in,
                              void* d_out, int out_size)
{
    const float* query = (const float*)d_in[0];
    const float* key   = (const float*)d_in[1];
    const float* value = (const float*)d_in[2];
    const float* boxes = (const float*)d_in[3];
    const float* Wq = (const float*)d_in[4];
    const float* bq = (const float*)d_in[5];
    const float* Wk = (const float*)d_in[6];
    const float* bk = (const float*)d_in[7];
    const float* Wv = (const float*)d_in[8];
    const float* bv = (const float*)d_in[9];
    const float* Wbox = (const float*)d_in[10];
    const float* bbox = (const float*)d_in[11];
    const float* Wo = (const float*)d_in[12];
    const float* bo = (const float*)d_in[13];

    float* out = (float*)d_out;
    float* attn_out = out + OUT_ELEMS;

    projA_kernel<<<dim3(28, 4, 2), 256>>>(query, key, value, boxes,
                                          Wq, bq, Wk, bk, Wv, bv, Wbox, bbox);
    projB_dots_kernel<<<256, 256>>>(Wo);
    softmax_kernel<<<128, 128>>>(attn_out);
    assemble_kernel<<<BB * NN * 4, 256>>>(bo, attn_out, out);
}

// round 10
// speedup vs baseline: 1.0600x; 1.0600x over previous
#include <cuda_runtime.h>
#include <math.h>
#include <stdint.h>

#define BB 2
#define NN 128
#define HH 2
#define DM 512
#define DK 256
#define BHN 512
#define SCALE 0.005524271728019903f   // 1/sqrt(128*256)
#define OUT_ELEMS (BB*NN*NN*DM)        // 16777216

// Split-K partials for projA outputs
__device__ float g_qp0[BHN*DK];
__device__ float g_qp1[BHN*DK];
__device__ float g_kp0[BHN*DK];
__device__ float g_kp1[BHN*DK];
__device__ float g_vp0[BHN*DK];
__device__ float g_vp1[BHN*DK];
__device__ float g_bxp0[BB*NN*DK];
__device__ float g_bxp1[BB*NN*DK];

__device__ float g_A[BHN];
__device__ float g_Bq[BHN];
__device__ float g_Ck[BHN];
__device__ float g_Dd[BB*NN];
__device__ float g_Vw[BHN*2*DM];       // [(bh,j)][hp][o]
__device__ float g_Bw[BB*NN*2*DM];     // [(b,j)][hp][o]

__device__ __forceinline__ float to_tf32(float x) {
    float r; asm("cvt.rna.tf32.f32 %0, %1;" : "=f"(r) : "f"(x)); return r;
}
__device__ __forceinline__ void mma_tf32(float* c,
        uint32_t a0, uint32_t a1, uint32_t a2, uint32_t a3,
        uint32_t b0, uint32_t b1) {
    asm volatile("mma.sync.aligned.m16n8k8.row.col.f32.tf32.tf32.f32 "
        "{%0,%1,%2,%3},{%4,%5,%6,%7},{%8,%9},{%0,%1,%2,%3};"
        : "+f"(c[0]), "+f"(c[1]), "+f"(c[2]), "+f"(c[3])
        : "r"(a0), "r"(a1), "r"(a2), "r"(a3), "r"(b0), "r"(b1));
}

// ---------------------------------------------------------------------------
// tf32 64x128 block GEMM core. 256 threads = 8 warps (2x4), warp tile 32x32.
// k-tile 16, double-buffered. Smem strides 72/136 (≡8 mod 32) keep fragment
// LDS conflict-free. SUM2: A operand = A[.] + A2[.] before tf32 conversion.
// ---------------------------------------------------------------------------
struct TCSmem {
    float sA[2][16][72];    // [buf][k][m]  9216 B
    float sB[2][16][136];   // [buf][k][n] 17408 B
};

template<int KC, bool SUM2>
__device__ __forceinline__ void gemm_tile_tc(const float* __restrict__ A,
        const float* __restrict__ A2, int astride,
        const float* __restrict__ W, int wcols, int row0, int col0,
        TCSmem& s, float cacc[2][4][4])
{
    const int t = threadIdx.x;
    const int lane = t & 31, warp = t >> 5;
    const int wm = (warp & 1) * 32, wn = (warp >> 1) * 32;
    const int gid = lane >> 2, tig = lane & 3;
    // A: 64 rows x 16 k = 1 float4/thread: row t>>2, k quad (t&3)*4
    const int a_r = t >> 2;
    const int a_q = (t & 3) * 4;
    // B: 16 k x 128 n = 2 passes: row (t>>5)+8l, col (t&31)*4
    const int b_k = t >> 5;
    const int b_c = (t & 31) * 4;
    constexpr int NK = KC / 16;

    float4 ra, rb[2];
    {
        size_t aoff = (size_t)(row0 + a_r) * astride + a_q;
        ra = *(const float4*)&A[aoff];
        if (SUM2) {
            float4 x = *(const float4*)&A2[aoff];
            ra.x += x.x; ra.y += x.y; ra.z += x.z; ra.w += x.w;
        }
#pragma unroll
        for (int l = 0; l < 2; ++l)
            rb[l] = *(const float4*)&W[(size_t)(b_k + 8 * l) * wcols + col0 + b_c];
    }
    {
        s.sA[0][a_q + 0][a_r] = to_tf32(ra.x);
        s.sA[0][a_q + 1][a_r] = to_tf32(ra.y);
        s.sA[0][a_q + 2][a_r] = to_tf32(ra.z);
        s.sA[0][a_q + 3][a_r] = to_tf32(ra.w);
#pragma unroll
        for (int l = 0; l < 2; ++l) {
            float4 tb;
            tb.x = to_tf32(rb[l].x); tb.y = to_tf32(rb[l].y);
            tb.z = to_tf32(rb[l].z); tb.w = to_tf32(rb[l].w);
            *(float4*)&s.sB[0][b_k + 8 * l][b_c] = tb;
        }
    }
    __syncthreads();

#pragma unroll
    for (int kt = 0; kt < NK; ++kt) {
        const int cur = kt & 1, nxt = cur ^ 1;
        if (kt + 1 < NK) {
            int k0 = (kt + 1) * 16;
            size_t aoff = (size_t)(row0 + a_r) * astride + k0 + a_q;
            ra = *(const float4*)&A[aoff];
            if (SUM2) {
                float4 x = *(const float4*)&A2[aoff];
                ra.x += x.x; ra.y += x.y; ra.z += x.z; ra.w += x.w;
            }
#pragma unroll
            for (int l = 0; l < 2; ++l)
                rb[l] = *(const float4*)&W[(size_t)(k0 + b_k + 8 * l) * wcols + col0 + b_c];
        }
#pragma unroll
        for (int kf = 0; kf < 16; kf += 8) {
            uint32_t af[2][4], bf[4][2];
#pragma unroll
            for (int mi = 0; mi < 2; ++mi) {
                int m0 = wm + mi * 16 + gid;
                af[mi][0] = __float_as_uint(s.sA[cur][kf + tig][m0]);
                af[mi][1] = __float_as_uint(s.sA[cur][kf + tig][m0 + 8]);
                af[mi][2] = __float_as_uint(s.sA[cur][kf + tig + 4][m0]);
                af[mi][3] = __float_as_uint(s.sA[cur][kf + tig + 4][m0 + 8]);
            }
#pragma unroll
            for (int ni = 0; ni < 4; ++ni) {
                int n0 = wn + ni * 8 + gid;
                bf[ni][0] = __float_as_uint(s.sB[cur][kf + tig][n0]);
                bf[ni][1] = __float_as_uint(s.sB[cur][kf + tig + 4][n0]);
            }
#pragma unroll
            for (int mi = 0; mi < 2; ++mi)
#pragma unroll
                for (int ni = 0; ni < 4; ++ni)
                    mma_tf32(cacc[mi][ni], af[mi][0], af[mi][1], af[mi][2], af[mi][3],
                             bf[ni][0], bf[ni][1]);
        }
        if (kt + 1 < NK) {
            s.sA[nxt][a_q + 0][a_r] = to_tf32(ra.x);
            s.sA[nxt][a_q + 1][a_r] = to_tf32(ra.y);
            s.sA[nxt][a_q + 2][a_r] = to_tf32(ra.z);
            s.sA[nxt][a_q + 3][a_r] = to_tf32(ra.w);
#pragma unroll
            for (int l = 0; l < 2; ++l) {
                float4 tb;
                tb.x = to_tf32(rb[l].x); tb.y = to_tf32(rb[l].y);
                tb.z = to_tf32(rb[l].z); tb.w = to_tf32(rb[l].w);
                *(float4*)&s.sB[nxt][b_k + 8 * l][b_c] = tb;
            }
        }
        __syncthreads();
    }
}

// ---------------------------------------------------------------------------
// Stage A: fused q/k/v/bx projections, split-K. grid=(14,4,2), 256 threads.
// col tiles of 128: ct 0-3 q, 4-7 k, 8-11 v, 12-13 bx. z = K-split.
// ---------------------------------------------------------------------------
__global__ __launch_bounds__(256) void projA_kernel(
    const float* __restrict__ query, const float* __restrict__ key,
    const float* __restrict__ value, const float* __restrict__ boxes,
    const float* __restrict__ Wq, const float* __restrict__ bq,
    const float* __restrict__ Wk, const float* __restrict__ bk,
    const float* __restrict__ Wv, const float* __restrict__ bv,
    const float* __restrict__ Wbox, const float* __restrict__ bbox)
{
    __shared__ TCSmem s;
    int ct = blockIdx.x;
    int which = (ct < 12) ? (ct >> 2) : 3;
    int col0 = (which < 3) ? (ct & 3) * 128 : (ct - 12) * 128;
    int row0 = blockIdx.y * 64;
    int z = blockIdx.z;

    const float* A; const float* W; const float* bias; float* out; int wcols;
    if      (which == 0) { A = query; W = Wq;   bias = bq;   out = z ? g_qp1  : g_qp0;  wcols = DM; }
    else if (which == 1) { A = key;   W = Wk;   bias = bk;   out = z ? g_kp1  : g_kp0;  wcols = DM; }
    else if (which == 2) { A = value; W = Wv;   bias = bv;   out = z ? g_vp1  : g_vp0;  wcols = DM; }
    else                 { A = boxes; W = Wbox; bias = bbox; out = z ? g_bxp1 : g_bxp0; wcols = DK; }

    float cacc[2][4][4];
#pragma unroll
    for (int mi = 0; mi < 2; ++mi)
#pragma unroll
        for (int ni = 0; ni < 4; ++ni)
#pragma unroll
            for (int r = 0; r < 4; ++r) cacc[mi][ni][r] = 0.f;

    gemm_tile_tc<256, false>(A + z * 256, nullptr, DM,
                             W + (size_t)z * 256 * wcols, wcols, row0, col0, s, cacc);

    const int lane = threadIdx.x & 31, warp = threadIdx.x >> 5;
    const int wm = (warp & 1) * 32, wn = (warp >> 1) * 32;
    const int gid = lane >> 2, tig = lane & 3;
#pragma unroll
    for (int mi = 0; mi < 2; ++mi)
#pragma unroll
        for (int rr = 0; rr < 2; ++rr) {
            int row = row0 + wm + mi * 16 + rr * 8 + gid;
            int b = row >> 7, n = row & 127;
#pragma unroll
            for (int ni = 0; ni < 4; ++ni) {
                int col = col0 + wn + ni * 8 + tig * 2;
                float2 v;
                float b0 = z ? 0.f : bias[col];
                float b1 = z ? 0.f : bias[col + 1];
                v.x = cacc[mi][ni][rr * 2 + 0] + b0;
                v.y = cacc[mi][ni][rr * 2 + 1] + b1;
                if (which < 3) {
                    int h = col >> 8, dk = col & 255;
                    *(float2*)&out[(((b * HH + h) * NN) + n) * DK + dk] = v;
                } else {
                    *(float2*)&out[row * DK + col] = v;
                }
            }
        }
}

// ---------------------------------------------------------------------------
// Fused Stage B + dots. Blocks 0..95: projB tiles (64x128).
// Blocks 96..159: dots. 256 threads.
// ---------------------------------------------------------------------------
__global__ __launch_bounds__(256) void projB_dots_kernel(const float* __restrict__ Wo)
{
    __shared__ TCSmem s;
    int p = blockIdx.x;

    if (p >= 96) {
        int w = threadIdx.x >> 5;
        int lane = threadIdx.x & 31;
        int bid = (p - 96) * 8 + w;
        int j = bid & 127;
        int bh = bid >> 7;
        int b = bh >> 1;

        const float4* q0 = (const float4*)(g_qp0 + (size_t)bid * DK);
        const float4* q1 = (const float4*)(g_qp1 + (size_t)bid * DK);
        const float4* k0 = (const float4*)(g_kp0 + (size_t)bid * DK);
        const float4* k1 = (const float4*)(g_kp1 + (size_t)bid * DK);
        const float4* x0 = (const float4*)(g_bxp0 + (size_t)(b * NN + j) * DK);
        const float4* x1 = (const float4*)(g_bxp1 + (size_t)(b * NN + j) * DK);

        float pa = 0.f, pb = 0.f, pc = 0.f, pd = 0.f;
#pragma unroll
        for (int u = 0; u < 2; ++u) {
            int d = lane + u * 32;
            float4 qa = q0[d], qb = q1[d], ka = k0[d], kb = k1[d], xa = x0[d], xb = x1[d];
            float4 qv, kv, bv;
            qv.x = qa.x + qb.x; qv.y = qa.y + qb.y; qv.z = qa.z + qb.z; qv.w = qa.w + qb.w;
            kv.x = ka.x + kb.x; kv.y = ka.y + kb.y; kv.z = ka.z + kb.z; kv.w = ka.w + kb.w;
            bv.x = xa.x + xb.x; bv.y = xa.y + xb.y; bv.z = xa.z + xb.z; bv.w = xa.w + xb.w;
            pa += qv.x*kv.x + qv.y*kv.y + qv.z*kv.z + qv.w*kv.w;
            pb += bv.x*kv.x + bv.y*kv.y + bv.z*kv.z + bv.w*kv.w;
            pc += qv.x*bv.x + qv.y*bv.y + qv.z*bv.z + qv.w*bv.w;
            pd += bv.x*bv.x + bv.y*bv.y + bv.z*bv.z + bv.w*bv.w;
        }
#pragma unroll
        for (int off = 16; off > 0; off >>= 1) {
            pa += __shfl_down_sync(0xffffffff, pa, off);
            pb += __shfl_down_sync(0xffffffff, pb, off);
            pc += __shfl_down_sync(0xffffffff, pc, off);
            pd += __shfl_down_sync(0xffffffff, pd, off);
        }
        if (lane == 0) {
            g_A[bid] = pa;
            g_Bq[bid] = pb;
            g_Ck[bid] = pc;
            if ((bh & 1) == 0) g_Dd[b * NN + j] = pd;
        }
        return;
    }

    // ---- projB tile: 64 rows x 128 cols ----
    int y = p >> 3;                    // 0..11
    int col0 = (p & 7) * 128;          // 0..896 over the 1024-wide [hp|o] axis
    int hp = col0 >> 9;                // which Wo half
    int wcol0 = col0 & 511;            // column inside that half
    const float *A, *A2; float* out; int row0;
    if (y < 8) { A = g_vp0;  A2 = g_vp1;  out = g_Vw; row0 = y * 64; }
    else       { A = g_bxp0; A2 = g_bxp1; out = g_Bw; row0 = (y - 8) * 64; }
    const float* W = Wo + (size_t)hp * DK * DM;

    float cacc[2][4][4];
#pragma unroll
    for (int mi = 0; mi < 2; ++mi)
#pragma unroll
        for (int ni = 0; ni < 4; ++ni)
#pragma unroll
            for (int r = 0; r < 4; ++r) cacc[mi][ni][r] = 0.f;

    gemm_tile_tc<DK, true>(A, A2, DK, W, DM, row0, wcol0, s, cacc);

    const int lane = threadIdx.x & 31, warp = threadIdx.x >> 5;
    const int wm = (warp & 1) * 32, wn = (warp >> 1) * 32;
    const int gid = lane >> 2, tig = lane & 3;
#pragma unroll
    for (int mi = 0; mi < 2; ++mi)
#pragma unroll
        for (int rr = 0; rr < 2; ++rr) {
            int row = row0 + wm + mi * 16 + rr * 8 + gid;
#pragma unroll
            for (int ni = 0; ni < 4; ++ni) {
                int col = wcol0 + wn + ni * 8 + tig * 2;
                float2 v;
                v.x = cacc[mi][ni][rr * 2 + 0];
                v.y = cacc[mi][ni][rr * 2 + 1];
                *(float2*)&out[(size_t)row * (2 * DM) + hp * DM + col] = v;
            }
        }
}

// ---------------------------------------------------------------------------
// Softmax: grid 128, 128 threads, warp per row.
// ---------------------------------------------------------------------------
__global__ __launch_bounds__(128) void softmax_kernel(float* __restrict__ attn_out)
{
    int warp = threadIdx.x >> 5, lane = threadIdx.x & 31;
    int t = threadIdx.x;
    int row_base = blockIdx.x * 4;
    int bh = row_base >> 7;
    int b = bh >> 1;

    __shared__ float sA[128], sCk[128];
    __shared__ float part[4];
    __shared__ float sS0;

    sA[t]  = g_A[bh * NN + t];
    sCk[t] = g_Ck[bh * NN + t];
    __syncthreads();
    {
        float v = sA[t];
#pragma unroll
        for (int off = 16; off > 0; off >>= 1)
            v += __shfl_down_sync(0xffffffff, v, off);
        if (lane == 0) part[warp] = v;
    }
    __syncthreads();
    if (t == 0) sS0 = part[0] + part[1] + part[2] + part[3];
    __syncthreads();
    float S0 = sS0;

    int n = (row_base & 127) + warp;
    float An = sA[n];
    float Bqn = g_Bq[bh * NN + n];
    float Ddn = g_Dd[b * NN + n];

    float sv[4], mx = -1e30f;
#pragma unroll
    for (int u = 0; u < 4; ++u) {
        int m = lane + u * 32;
        float x = (m == n) ? (S0 - An + Ddn)
                           : (S0 - An - sA[m] + Bqn + sCk[m]);
        sv[u] = x * SCALE;
        mx = fmaxf(mx, sv[u]);
    }
#pragma unroll
    for (int off = 16; off > 0; off >>= 1)
        mx = fmaxf(mx, __shfl_xor_sync(0xffffffff, mx, off));
    float e[4], tot = 0.f;
#pragma unroll
    for (int u = 0; u < 4; ++u) { e[u] = expf(sv[u] - mx); tot += e[u]; }
#pragma unroll
    for (int off = 16; off > 0; off >>= 1)
        tot += __shfl_xor_sync(0xffffffff, tot, off);
    float inv = 1.f / tot;
    size_t base = ((size_t)(bh * NN) + n) * NN;
#pragma unroll
    for (int u = 0; u < 4; ++u)
        attn_out[base + lane + u * 32] = e[u] * inv;
}

// ---------------------------------------------------------------------------
// Assembly (R8 version): sync-free, zero smem, pipelined shfl broadcast.
// Block per (b, jp, iq): 1024 x 256. out[b,i,jp,:] = base + a0*d0 + a1*d1
// ---------------------------------------------------------------------------
__global__ __launch_bounds__(256) void assemble_kernel(
    const float* __restrict__ bo, const float* __restrict__ attn,
    float* __restrict__ out)
{
    int bid = blockIdx.x;
    int iq = bid & 3;
    int bjp = bid >> 2;
    int jp = bjp & 127, b = bjp >> 7;
    int h = jp >> 6, jj = jp & 63;
    int j0 = 2 * jj, j1 = j0 + 1;
    int bh = b * HH + h;

    int t = threadIdx.x;
    int lane = t & 31;
    int sub = t >> 7;
    int c4 = (t & 127) * 4;

    int itn = lane & 15;
    int i_pre = iq * 32 + itn * 2 + sub;
    float aval = attn[((size_t)(bh * NN) + i_pre) * NN + j0 + (lane >> 4)];

    float4 v0 = *(const float4*)&g_Vw[(size_t)((bh * NN + j0) * 2 + 0) * DM + c4];
    float4 v1 = *(const float4*)&g_Vw[(size_t)((bh * NN + j1) * 2 + 1) * DM + c4];
    float4 w0 = *(const float4*)&g_Bw[(size_t)((b  * NN + j0) * 2 + 0) * DM + c4];
    float4 w1 = *(const float4*)&g_Bw[(size_t)((b  * NN + j1) * 2 + 1) * DM + c4];
    float4 bb = *(const float4*)&bo[c4];

    float4 rb, r0, r1;
    rb.x = v0.x + v1.x + bb.x; rb.y = v0.y + v1.y + bb.y;
    rb.z = v0.z + v1.z + bb.z; rb.w = v0.w + v1.w + bb.w;
    r0.x = w0.x - v0.x; r0.y = w0.y - v0.y; r0.z = w0.z - v0.z; r0.w = w0.w - v0.w;
    r1.x = w1.x - v1.x; r1.y = w1.y - v1.y; r1.z = w1.z - v1.z; r1.w = w1.w - v1.w;

    float a0c = __shfl_sync(0xffffffff, aval, 0);
    float a1c = __shfl_sync(0xffffffff, aval, 16);
#pragma unroll
    for (int it = 0; it < 16; ++it) {
        float a0 = a0c, a1 = a1c;
        if (it < 15) {
            a0c = __shfl_sync(0xffffffff, aval, it + 1);
            a1c = __shfl_sync(0xffffffff, aval, it + 17);
        }
        int i = iq * 32 + it * 2 + sub;
        float4 r;
        r.x = rb.x + a0 * r0.x + a1 * r1.x;
        r.y = rb.y + a0 * r0.y + a1 * r1.y;
        r.z = rb.z + a0 * r0.z + a1 * r1.z;
        r.w = rb.w + a0 * r0.w + a1 * r1.w;
        *(float4*)&out[(((size_t)(b * NN + i) * NN) + jp) * DM + c4] = r;
    }
}

// ---------------------------------------------------------------------------
extern "C" void kernel_launch(void* const* d_in, const int* in_sizes, int n_in,
                              void* d_out, int out_size)
{
    const float* query = (const float*)d_in[0];
    const float* key   = (const float*)d_in[1];
    const float* value = (const float*)d_in[2];
    const float* boxes = (const float*)d_in[3];
    const float* Wq = (const float*)d_in[4];
    const float* bq = (const float*)d_in[5];
    const float* Wk = (const float*)d_in[6];
    const float* bk = (const float*)d_in[7];
    const float* Wv = (const float*)d_in[8];
    const float* bv = (const float*)d_in[9];
    const float* Wbox = (const float*)d_in[10];
    const float* bbox = (const float*)d_in[11];
    const float* Wo = (const float*)d_in[12];
    const float* bo = (const float*)d_in[13];

    float* out = (float*)d_out;
    float* attn_out = out + OUT_ELEMS;

    projA_kernel<<<dim3(14, 4, 2), 256>>>(query, key, value, boxes,
                                          Wq, bq, Wk, bk, Wv, bv, Wbox, bbox);
    projB_dots_kernel<<<160, 256>>>(Wo);
    softmax_kernel<<<128, 128>>>(attn_out);
    assemble_kernel<<<BB * NN * 4, 256>>>(bo, attn_out, out);
}

// round 11
// speedup vs baseline: 1.2230x; 1.1538x over previous
#include <cuda_runtime.h>
#include <math.h>
#include <stdint.h>

#define BB 2
#define NN 128
#define HH 2
#define DM 512
#define DK 256
#define BHN 512
#define SCALE 0.005524271728019903f   // 1/sqrt(128*256)
#define OUT_ELEMS (BB*NN*NN*DM)        // 16777216

// projA split-K=4 partials
__device__ float g_qp[4][BHN*DK];
__device__ float g_kp[4][BHN*DK];
__device__ float g_vp[4][BHN*DK];
__device__ float g_bxp[4][BB*NN*DK];

__device__ float g_A[BHN];
__device__ float g_Bq[BHN];
__device__ float g_Ck[BHN];
__device__ float g_Dd[BB*NN];

// projB split-K=2 partials
__device__ float g_Vw[2][BHN*2*DM];     // [(bh,j)][hp][o]
__device__ float g_Bw[2][BB*NN*2*DM];   // [(b,j)][hp][o]

__device__ unsigned g_cnt;               // dots completion counter

__device__ __forceinline__ float to_tf32(float x) {
    float r; asm("cvt.rna.tf32.f32 %0, %1;" : "=f"(r) : "f"(x)); return r;
}
__device__ __forceinline__ void mma_tf32(float* c,
        uint32_t a0, uint32_t a1, uint32_t a2, uint32_t a3,
        uint32_t b0, uint32_t b1) {
    asm volatile("mma.sync.aligned.m16n8k8.row.col.f32.tf32.tf32.f32 "
        "{%0,%1,%2,%3},{%4,%5,%6,%7},{%8,%9},{%0,%1,%2,%3};"
        : "+f"(c[0]), "+f"(c[1]), "+f"(c[2]), "+f"(c[3])
        : "r"(a0), "r"(a1), "r"(a2), "r"(a3), "r"(b0), "r"(b1));
}

// ---------------------------------------------------------------------------
// tf32 64x128 block GEMM core. 256 threads = 8 warps (2x4), warp tile 32x32.
// k-tile 16, double-buffered. NSUM: A operand = sum of NSUM partial arrays.
// ---------------------------------------------------------------------------
struct TCSmem {
    float sA[2][16][72];
    float sB[2][16][136];
};

template<int KC, int NSUM>
__device__ __forceinline__ void gemm_tile_tc(
        const float* __restrict__ A0, const float* __restrict__ A1,
        const float* __restrict__ A2, const float* __restrict__ A3,
        int astride,
        const float* __restrict__ W, int wcols, int row0, int col0,
        TCSmem& s, float cacc[2][4][4])
{
    const int t = threadIdx.x;
    const int lane = t & 31, warp = t >> 5;
    const int wm = (warp & 1) * 32, wn = (warp >> 1) * 32;
    const int gid = lane >> 2, tig = lane & 3;
    const int a_r = t >> 2;
    const int a_q = (t & 3) * 4;
    const int b_k = t >> 5;
    const int b_c = (t & 31) * 4;
    constexpr int NK = KC / 16;

    auto loadA = [&](int k0) -> float4 {
        size_t off = (size_t)(row0 + a_r) * astride + k0 + a_q;
        float4 r = *(const float4*)&A0[off];
        if (NSUM > 1) {
            float4 x = *(const float4*)&A1[off];
            r.x += x.x; r.y += x.y; r.z += x.z; r.w += x.w;
        }
        if (NSUM > 2) {
            float4 x = *(const float4*)&A2[off];
            r.x += x.x; r.y += x.y; r.z += x.z; r.w += x.w;
            x = *(const float4*)&A3[off];
            r.x += x.x; r.y += x.y; r.z += x.z; r.w += x.w;
        }
        return r;
    };

    float4 ra, rb[2];
    ra = loadA(0);
#pragma unroll
    for (int l = 0; l < 2; ++l)
        rb[l] = *(const float4*)&W[(size_t)(b_k + 8 * l) * wcols + col0 + b_c];
    {
        s.sA[0][a_q + 0][a_r] = to_tf32(ra.x);
        s.sA[0][a_q + 1][a_r] = to_tf32(ra.y);
        s.sA[0][a_q + 2][a_r] = to_tf32(ra.z);
        s.sA[0][a_q + 3][a_r] = to_tf32(ra.w);
#pragma unroll
        for (int l = 0; l < 2; ++l) {
            float4 tb;
            tb.x = to_tf32(rb[l].x); tb.y = to_tf32(rb[l].y);
            tb.z = to_tf32(rb[l].z); tb.w = to_tf32(rb[l].w);
            *(float4*)&s.sB[0][b_k + 8 * l][b_c] = tb;
        }
    }
    __syncthreads();

#pragma unroll
    for (int kt = 0; kt < NK; ++kt) {
        const int cur = kt & 1, nxt = cur ^ 1;
        if (kt + 1 < NK) {
            int k0 = (kt + 1) * 16;
            ra = loadA(k0);
#pragma unroll
            for (int l = 0; l < 2; ++l)
                rb[l] = *(const float4*)&W[(size_t)(k0 + b_k + 8 * l) * wcols + col0 + b_c];
        }
#pragma unroll
        for (int kf = 0; kf < 16; kf += 8) {
            uint32_t af[2][4], bf[4][2];
#pragma unroll
            for (int mi = 0; mi < 2; ++mi) {
                int m0 = wm + mi * 16 + gid;
                af[mi][0] = __float_as_uint(s.sA[cur][kf + tig][m0]);
                af[mi][1] = __float_as_uint(s.sA[cur][kf + tig][m0 + 8]);
                af[mi][2] = __float_as_uint(s.sA[cur][kf + tig + 4][m0]);
                af[mi][3] = __float_as_uint(s.sA[cur][kf + tig + 4][m0 + 8]);
            }
#pragma unroll
            for (int ni = 0; ni < 4; ++ni) {
                int n0 = wn + ni * 8 + gid;
                bf[ni][0] = __float_as_uint(s.sB[cur][kf + tig][n0]);
                bf[ni][1] = __float_as_uint(s.sB[cur][kf + tig + 4][n0]);
            }
#pragma unroll
            for (int mi = 0; mi < 2; ++mi)
#pragma unroll
                for (int ni = 0; ni < 4; ++ni)
                    mma_tf32(cacc[mi][ni], af[mi][0], af[mi][1], af[mi][2], af[mi][3],
                             bf[ni][0], bf[ni][1]);
        }
        if (kt + 1 < NK) {
            s.sA[nxt][a_q + 0][a_r] = to_tf32(ra.x);
            s.sA[nxt][a_q + 1][a_r] = to_tf32(ra.y);
            s.sA[nxt][a_q + 2][a_r] = to_tf32(ra.z);
            s.sA[nxt][a_q + 3][a_r] = to_tf32(ra.w);
#pragma unroll
            for (int l = 0; l < 2; ++l) {
                float4 tb;
                tb.x = to_tf32(rb[l].x); tb.y = to_tf32(rb[l].y);
                tb.z = to_tf32(rb[l].z); tb.w = to_tf32(rb[l].w);
                *(float4*)&s.sB[nxt][b_k + 8 * l][b_c] = tb;
            }
        }
        __syncthreads();
    }
}

// ---------------------------------------------------------------------------
// Stage A: fused q/k/v/bx projections, split-K=4. grid=(14,4,4), 256 threads.
// Block (0,0,0) thread 0 resets the stage2 counter (stream-ordered).
// ---------------------------------------------------------------------------
__global__ __launch_bounds__(256) void projA_kernel(
    const float* __restrict__ query, const float* __restrict__ key,
    const float* __restrict__ value, const float* __restrict__ boxes,
    const float* __restrict__ Wq, const float* __restrict__ bq,
    const float* __restrict__ Wk, const float* __restrict__ bk,
    const float* __restrict__ Wv, const float* __restrict__ bv,
    const float* __restrict__ Wbox, const float* __restrict__ bbox)
{
    __shared__ TCSmem s;
    if (blockIdx.x == 0 && blockIdx.y == 0 && blockIdx.z == 0 && threadIdx.x == 0)
        g_cnt = 0u;

    int ct = blockIdx.x;
    int which = (ct < 12) ? (ct >> 2) : 3;
    int col0 = (which < 3) ? (ct & 3) * 128 : (ct - 12) * 128;
    int row0 = blockIdx.y * 64;
    int z = blockIdx.z;

    const float* A; const float* W; const float* bias; float* out; int wcols;
    if      (which == 0) { A = query; W = Wq;   bias = bq;   out = g_qp[z];  wcols = DM; }
    else if (which == 1) { A = key;   W = Wk;   bias = bk;   out = g_kp[z];  wcols = DM; }
    else if (which == 2) { A = value; W = Wv;   bias = bv;   out = g_vp[z];  wcols = DM; }
    else                 { A = boxes; W = Wbox; bias = bbox; out = g_bxp[z]; wcols = DK; }

    float cacc[2][4][4];
#pragma unroll
    for (int mi = 0; mi < 2; ++mi)
#pragma unroll
        for (int ni = 0; ni < 4; ++ni)
#pragma unroll
            for (int r = 0; r < 4; ++r) cacc[mi][ni][r] = 0.f;

    gemm_tile_tc<128, 1>(A + z * 128, nullptr, nullptr, nullptr, DM,
                         W + (size_t)z * 128 * wcols, wcols, row0, col0, s, cacc);

    const int lane = threadIdx.x & 31, warp = threadIdx.x >> 5;
    const int wm = (warp & 1) * 32, wn = (warp >> 1) * 32;
    const int gid = lane >> 2, tig = lane & 3;
#pragma unroll
    for (int mi = 0; mi < 2; ++mi)
#pragma unroll
        for (int rr = 0; rr < 2; ++rr) {
            int row = row0 + wm + mi * 16 + rr * 8 + gid;
            int b = row >> 7, n = row & 127;
#pragma unroll
            for (int ni = 0; ni < 4; ++ni) {
                int col = col0 + wn + ni * 8 + tig * 2;
                float2 v;
                float b0 = z ? 0.f : bias[col];
                float b1 = z ? 0.f : bias[col + 1];
                v.x = cacc[mi][ni][rr * 2 + 0] + b0;
                v.y = cacc[mi][ni][rr * 2 + 1] + b1;
                if (which < 3) {
                    int h = col >> 8, dk = col & 255;
                    *(float2*)&out[(((b * HH + h) * NN) + n) * DK + dk] = v;
                } else {
                    *(float2*)&out[row * DK + col] = v;
                }
            }
        }
}

// ---------------------------------------------------------------------------
// Stage 2: blocks 0..63 = dots -> barrier(counter) -> softmax.
//          blocks 64..255 = projB GEMM (split-K 2, 64x128 tiles).
// Attn chain overlaps GEMM execution within one launch.
// ---------------------------------------------------------------------------
__global__ __launch_bounds__(256) void stage2_kernel(
    const float* __restrict__ Wo, float* __restrict__ attn_out)
{
    __shared__ TCSmem s;
    int p = blockIdx.x;
    int t = threadIdx.x;
    int warp = t >> 5, lane = t & 31;

    if (p < 64) {
        // ===== dots: warp per (bh,j) =====
        int bid = p * 8 + warp;      // 0..511
        int j = bid & 127;
        int bh_d = bid >> 7;
        int b_d = bh_d >> 1;

        float pa = 0.f, pb = 0.f, pc = 0.f, pd = 0.f;
#pragma unroll
        for (int u = 0; u < 2; ++u) {
            int d = lane + u * 32;
            float4 qv, kv, bv;
            {
                const float4* a0 = (const float4*)(g_qp[0] + (size_t)bid * DK);
                const float4* a1 = (const float4*)(g_qp[1] + (size_t)bid * DK);
                const float4* a2 = (const float4*)(g_qp[2] + (size_t)bid * DK);
                const float4* a3 = (const float4*)(g_qp[3] + (size_t)bid * DK);
                float4 x0 = a0[d], x1 = a1[d], x2 = a2[d], x3 = a3[d];
                qv.x = x0.x + x1.x + x2.x + x3.x; qv.y = x0.y + x1.y + x2.y + x3.y;
                qv.z = x0.z + x1.z + x2.z + x3.z; qv.w = x0.w + x1.w + x2.w + x3.w;
            }
            {
                const float4* a0 = (const float4*)(g_kp[0] + (size_t)bid * DK);
                const float4* a1 = (const float4*)(g_kp[1] + (size_t)bid * DK);
                const float4* a2 = (const float4*)(g_kp[2] + (size_t)bid * DK);
                const float4* a3 = (const float4*)(g_kp[3] + (size_t)bid * DK);
                float4 x0 = a0[d], x1 = a1[d], x2 = a2[d], x3 = a3[d];
                kv.x = x0.x + x1.x + x2.x + x3.x; kv.y = x0.y + x1.y + x2.y + x3.y;
                kv.z = x0.z + x1.z + x2.z + x3.z; kv.w = x0.w + x1.w + x2.w + x3.w;
            }
            {
                size_t boff = (size_t)(b_d * NN + j) * DK;
                const float4* a0 = (const float4*)(g_bxp[0] + boff);
                const float4* a1 = (const float4*)(g_bxp[1] + boff);
                const float4* a2 = (const float4*)(g_bxp[2] + boff);
                const float4* a3 = (const float4*)(g_bxp[3] + boff);
                float4 x0 = a0[d], x1 = a1[d], x2 = a2[d], x3 = a3[d];
                bv.x = x0.x + x1.x + x2.x + x3.x; bv.y = x0.y + x1.y + x2.y + x3.y;
                bv.z = x0.z + x1.z + x2.z + x3.z; bv.w = x0.w + x1.w + x2.w + x3.w;
            }
            pa += qv.x*kv.x + qv.y*kv.y + qv.z*kv.z + qv.w*kv.w;
            pb += bv.x*kv.x + bv.y*kv.y + bv.z*kv.z + bv.w*kv.w;
            pc += qv.x*bv.x + qv.y*bv.y + qv.z*bv.z + qv.w*bv.w;
            pd += bv.x*bv.x + bv.y*bv.y + bv.z*bv.z + bv.w*bv.w;
        }
#pragma unroll
        for (int off = 16; off > 0; off >>= 1) {
            pa += __shfl_down_sync(0xffffffff, pa, off);
            pb += __shfl_down_sync(0xffffffff, pb, off);
            pc += __shfl_down_sync(0xffffffff, pc, off);
            pd += __shfl_down_sync(0xffffffff, pd, off);
        }
        if (lane == 0) {
            g_A[bid] = pa;
            g_Bq[bid] = pb;
            g_Ck[bid] = pc;
            if ((bh_d & 1) == 0) g_Dd[b_d * NN + j] = pd;
        }
        __syncthreads();

        // ===== global barrier over the 64 dots blocks =====
        if (t == 0) {
            __threadfence();
            atomicAdd(&g_cnt, 1u);
            while (atomicAdd(&g_cnt, 0u) < 64u) __nanosleep(64);
        }
        __syncthreads();
        __threadfence();

        // ===== softmax: warp per row, 8 rows per block =====
        int bh = p >> 4;
        int b = bh >> 1;
        __shared__ float sA[128], sCk[128];
        if (t < 128) sA[t] = g_A[bh * NN + t];
        else         sCk[t - 128] = g_Ck[bh * NN + (t - 128)];
        __syncthreads();

        float v = sA[lane] + sA[lane + 32] + sA[lane + 64] + sA[lane + 96];
#pragma unroll
        for (int off = 16; off > 0; off >>= 1)
            v += __shfl_down_sync(0xffffffff, v, off);
        float S0 = __shfl_sync(0xffffffff, v, 0);

        int n = (p & 15) * 8 + warp;
        float An = sA[n];
        float Bqn = g_Bq[bh * NN + n];
        float Ddn = g_Dd[b * NN + n];

        float sv[4], mx = -1e30f;
#pragma unroll
        for (int u = 0; u < 4; ++u) {
            int m = lane + u * 32;
            float x = (m == n) ? (S0 - An + Ddn)
                               : (S0 - An - sA[m] + Bqn + sCk[m]);
            sv[u] = x * SCALE;
            mx = fmaxf(mx, sv[u]);
        }
#pragma unroll
        for (int off = 16; off > 0; off >>= 1)
            mx = fmaxf(mx, __shfl_xor_sync(0xffffffff, mx, off));
        float e[4], tot = 0.f;
#pragma unroll
        for (int u = 0; u < 4; ++u) { e[u] = expf(sv[u] - mx); tot += e[u]; }
#pragma unroll
        for (int off = 16; off > 0; off >>= 1)
            tot += __shfl_xor_sync(0xffffffff, tot, off);
        float inv = 1.f / tot;
        size_t base = ((size_t)(bh * NN) + n) * NN;
#pragma unroll
        for (int u = 0; u < 4; ++u)
            attn_out[base + lane + u * 32] = e[u] * inv;
        return;
    }

    // ===== projB GEMM: split-K 2, 64x128 tiles =====
    int idx = p - 64;              // 0..191
    int y = idx >> 4;              // 0..11
    int rem = idx & 15;
    int colt = rem >> 1;           // 0..7
    int ks = rem & 1;
    int col0 = colt * 128;
    int hp = col0 >> 9;
    int wcol0 = col0 & 511;

    const float *A0, *A1, *A2, *A3; float* out; int row0;
    if (y < 8) {
        A0 = g_vp[0]; A1 = g_vp[1]; A2 = g_vp[2]; A3 = g_vp[3];
        out = g_Vw[ks]; row0 = y * 64;
    } else {
        A0 = g_bxp[0]; A1 = g_bxp[1]; A2 = g_bxp[2]; A3 = g_bxp[3];
        out = g_Bw[ks]; row0 = (y - 8) * 64;
    }
    const float* W = Wo + (size_t)hp * DK * DM + (size_t)ks * 128 * DM;

    float cacc[2][4][4];
#pragma unroll
    for (int mi = 0; mi < 2; ++mi)
#pragma unroll
        for (int ni = 0; ni < 4; ++ni)
#pragma unroll
            for (int r = 0; r < 4; ++r) cacc[mi][ni][r] = 0.f;

    gemm_tile_tc<128, 4>(A0 + ks * 128, A1 + ks * 128, A2 + ks * 128, A3 + ks * 128,
                         DK, W, DM, row0, wcol0, s, cacc);

    const int wm = (warp & 1) * 32, wn = (warp >> 1) * 32;
    const int gid = lane >> 2, tig = lane & 3;
#pragma unroll
    for (int mi = 0; mi < 2; ++mi)
#pragma unroll
        for (int rr = 0; rr < 2; ++rr) {
            int row = row0 + wm + mi * 16 + rr * 8 + gid;
#pragma unroll
            for (int ni = 0; ni < 4; ++ni) {
                int col = wcol0 + wn + ni * 8 + tig * 2;
                float2 v;
                v.x = cacc[mi][ni][rr * 2 + 0];
                v.y = cacc[mi][ni][rr * 2 + 1];
                *(float2*)&out[(size_t)row * (2 * DM) + hp * DM + col] = v;
            }
        }
}

// ---------------------------------------------------------------------------
// Assembly: sync-free, zero smem, pipelined shfl broadcast; sums the two
// projB split-K partials. Block per (b, jp, iq): 1024 x 256.
// ---------------------------------------------------------------------------
__global__ __launch_bounds__(256) void assemble_kernel(
    const float* __restrict__ bo, const float* __restrict__ attn,
    float* __restrict__ out)
{
    int bid = blockIdx.x;
    int iq = bid & 3;
    int bjp = bid >> 2;
    int jp = bjp & 127, b = bjp >> 7;
    int h = jp >> 6, jj = jp & 63;
    int j0 = 2 * jj, j1 = j0 + 1;
    int bh = b * HH + h;

    int t = threadIdx.x;
    int lane = t & 31;
    int sub = t >> 7;
    int c4 = (t & 127) * 4;

    int itn = lane & 15;
    int i_pre = iq * 32 + itn * 2 + sub;
    float aval = attn[((size_t)(bh * NN) + i_pre) * NN + j0 + (lane >> 4)];

    size_t iv0 = (size_t)((bh * NN + j0) * 2 + 0) * DM + c4;
    size_t iv1 = (size_t)((bh * NN + j1) * 2 + 1) * DM + c4;
    size_t iw0 = (size_t)((b  * NN + j0) * 2 + 0) * DM + c4;
    size_t iw1 = (size_t)((b  * NN + j1) * 2 + 1) * DM + c4;

    float4 v0 = *(const float4*)&g_Vw[0][iv0];
    float4 x  = *(const float4*)&g_Vw[1][iv0];
    v0.x += x.x; v0.y += x.y; v0.z += x.z; v0.w += x.w;
    float4 v1 = *(const float4*)&g_Vw[0][iv1];
    x = *(const float4*)&g_Vw[1][iv1];
    v1.x += x.x; v1.y += x.y; v1.z += x.z; v1.w += x.w;
    float4 w0 = *(const float4*)&g_Bw[0][iw0];
    x = *(const float4*)&g_Bw[1][iw0];
    w0.x += x.x; w0.y += x.y; w0.z += x.z; w0.w += x.w;
    float4 w1 = *(const float4*)&g_Bw[0][iw1];
    x = *(const float4*)&g_Bw[1][iw1];
    w1.x += x.x; w1.y += x.y; w1.z += x.z; w1.w += x.w;
    float4 bb = *(const float4*)&bo[c4];

    float4 rb, r0, r1;
    rb.x = v0.x + v1.x + bb.x; rb.y = v0.y + v1.y + bb.y;
    rb.z = v0.z + v1.z + bb.z; rb.w = v0.w + v1.w + bb.w;
    r0.x = w0.x - v0.x; r0.y = w0.y - v0.y; r0.z = w0.z - v0.z; r0.w = w0.w - v0.w;
    r1.x = w1.x - v1.x; r1.y = w1.y - v1.y; r1.z = w1.z - v1.z; r1.w = w1.w - v1.w;

    float a0c = __shfl_sync(0xffffffff, aval, 0);
    float a1c = __shfl_sync(0xffffffff, aval, 16);
#pragma unroll
    for (int it = 0; it < 16; ++it) {
        float a0 = a0c, a1 = a1c;
        if (it < 15) {
            a0c = __shfl_sync(0xffffffff, aval, it + 1);
            a1c = __shfl_sync(0xffffffff, aval, it + 17);
        }
        int i = iq * 32 + it * 2 + sub;
        float4 r;
        r.x = rb.x + a0 * r0.x + a1 * r1.x;
        r.y = rb.y + a0 * r0.y + a1 * r1.y;
        r.z = rb.z + a0 * r0.z + a1 * r1.z;
        r.w = rb.w + a0 * r0.w + a1 * r1.w;
        *(float4*)&out[(((size_t)(b * NN + i) * NN) + jp) * DM + c4] = r;
    }
}

// ---------------------------------------------------------------------------
extern "C" void kernel_launch(void* const* d_in, const int* in_sizes, int n_in,
                              void* d_out, int out_size)
{
    const float* query = (const float*)d_in[0];
    const float* key   = (const float*)d_in[1];
    const float* value = (const float*)d_in[2];
    const float* boxes = (const float*)d_in[3];
    const float* Wq = (const float*)d_in[4];
    const float* bq = (const float*)d_in[5];
    const float* Wk = (const float*)d_in[6];
    const float* bk = (const float*)d_in[7];
    const float* Wv = (const float*)d_in[8];
    const float* bv = (const float*)d_in[9];
    const float* Wbox = (const float*)d_in[10];
    const float* bbox = (const float*)d_in[11];
    const float* Wo = (const float*)d_in[12];
    const float* bo = (const float*)d_in[13];

    float* out = (float*)d_out;
    float* attn_out = out + OUT_ELEMS;

    projA_kernel<<<dim3(14, 4, 4), 256>>>(query, key, value, boxes,
                                          Wq, bq, Wk, bk, Wv, bv, Wbox, bbox);
    stage2_kernel<<<256, 256>>>(Wo, attn_out);
    assemble_kernel<<<BB * NN * 4, 256>>>(bo, attn_out, out);
}